// round 4
// baseline (speedup 1.0000x reference)
#include <cuda_runtime.h>
#include <math.h>

// ---------------- problem constants ----------------
#define Bb     2
#define Ss     2048
#define DIMc   2048
#define Hh     16
#define QLORA  1536
#define KVLORA 512
#define NOPEc  128
#define ROPEc  64
#define VDIMc  128
#define QKH    192            // NOPE + ROPE
#define ROWS   (Bb*Ss)        // 4096
#define DF     576            // 512 latent + 64 rope
#define SCALEc 0.07216878364870322f  // 1/sqrt(192)
#define EPSc   1e-6f

// ---------------- scratch (static device arrays; no allocation) ----------------
__device__ float g_qlat[(size_t)ROWS * QLORA];          // 4096 x 1536
__device__ float g_q[(size_t)ROWS * (Hh * QKH)];        // 4096 x 3072
__device__ float g_kv[(size_t)ROWS * DF];               // 4096 x 576 (raw kv_a output)
__device__ float g_kfull[(size_t)ROWS * DF];            // 4096 x 576 (normed latent + roped kpe)
__device__ float g_qfull[(size_t)ROWS * Hh * DF];       // 4096 x 16 x 576 (absorbed q + roped qpe)
__device__ float g_ctx[(size_t)ROWS * Hh * KVLORA];     // 4096 x 16 x 512
__device__ float g_attnout[(size_t)ROWS * DIMc];        // 4096 x 2048

// ---------------- generic tiled fp32 GEMM ----------------
// C[M,N] = A[M,K] @ op(B). TB=true: B is [N,K] row-major (C = A B^T).
//                           TB=false: B is [K,N] row-major (C = A B).
// Batched over grid.z with element strides sA/sB/sC.
#define GBM 128
#define GBN 128
#define GBK 8

template<bool TB>
__global__ __launch_bounds__(256) void gemm_kernel(
    const float* __restrict__ A, int lda, long sA,
    const float* __restrict__ B, int ldb, long sB,
    float* __restrict__ C, int ldc, long sC,
    int M, int N, int K)
{
    __shared__ float As[GBK][GBM + 4];
    __shared__ float Bs[GBK][GBN + 4];

    int z = blockIdx.z;
    A += (size_t)z * sA;
    B += (size_t)z * sB;
    C += (size_t)z * sC;

    int tid = threadIdx.x;
    int m0 = blockIdx.y * GBM;
    int n0 = blockIdx.x * GBN;
    int ti = tid >> 4;        // 0..15 row group
    int tj = tid & 15;        // 0..15 col group

    int lrow = tid >> 1;      // 0..127
    int lk   = (tid & 1) * 4; // 0 or 4

    float acc[8][8];
#pragma unroll
    for (int i = 0; i < 8; i++)
#pragma unroll
        for (int j = 0; j < 8; j++) acc[i][j] = 0.f;

    for (int k0 = 0; k0 < K; k0 += GBK) {
        // load A tile (transpose into As[k][m])
        {
            float4 av = *(const float4*)(A + (size_t)(m0 + lrow) * lda + k0 + lk);
            As[lk + 0][lrow] = av.x;
            As[lk + 1][lrow] = av.y;
            As[lk + 2][lrow] = av.z;
            As[lk + 3][lrow] = av.w;
        }
        // load B tile into Bs[k][n]
        if (TB) {
            int n = n0 + lrow;
            float4 bv = make_float4(0.f, 0.f, 0.f, 0.f);
            if (n < N) bv = *(const float4*)(B + (size_t)n * ldb + k0 + lk);
            Bs[lk + 0][lrow] = bv.x;
            Bs[lk + 1][lrow] = bv.y;
            Bs[lk + 2][lrow] = bv.z;
            Bs[lk + 3][lrow] = bv.w;
        } else {
            int bk = tid >> 5;          // 0..7
            int bn = (tid & 31) * 4;    // 0..124
            float4 bv = make_float4(0.f, 0.f, 0.f, 0.f);
            if (n0 + bn < N) bv = *(const float4*)(B + (size_t)(k0 + bk) * ldb + n0 + bn);
            *(float4*)&Bs[bk][bn] = bv;
        }
        __syncthreads();

#pragma unroll
        for (int k = 0; k < GBK; k++) {
            float a[8], b[8];
            float4 t;
            t = *(const float4*)&As[k][ti * 8];     a[0]=t.x; a[1]=t.y; a[2]=t.z; a[3]=t.w;
            t = *(const float4*)&As[k][ti * 8 + 4]; a[4]=t.x; a[5]=t.y; a[6]=t.z; a[7]=t.w;
            t = *(const float4*)&Bs[k][tj * 8];     b[0]=t.x; b[1]=t.y; b[2]=t.z; b[3]=t.w;
            t = *(const float4*)&Bs[k][tj * 8 + 4]; b[4]=t.x; b[5]=t.y; b[6]=t.z; b[7]=t.w;
#pragma unroll
            for (int i = 0; i < 8; i++)
#pragma unroll
                for (int j = 0; j < 8; j++)
                    acc[i][j] = fmaf(a[i], b[j], acc[i][j]);
        }
        __syncthreads();
    }

#pragma unroll
    for (int i = 0; i < 8; i++) {
        int m = m0 + ti * 8 + i;
        float* cp = C + (size_t)m * ldc + n0 + tj * 8;
#pragma unroll
        for (int j = 0; j < 8; j += 4) {
            if (n0 + tj * 8 + j < N) {
                float4 v = make_float4(acc[i][j], acc[i][j+1], acc[i][j+2], acc[i][j+3]);
                *(float4*)(cp + j) = v;
            }
        }
    }
}

// ---------------- RMSNorm (in-place, one block per row) ----------------
__global__ __launch_bounds__(256) void rmsnorm_kernel(
    float* __restrict__ x, const float* __restrict__ w, int L)
{
    __shared__ float sbuf[8];
    int row = blockIdx.x;
    float* xr = x + (size_t)row * L;
    float ss = 0.f;
    for (int i = threadIdx.x; i < L; i += 256) { float v = xr[i]; ss += v * v; }
#pragma unroll
    for (int o = 16; o; o >>= 1) ss += __shfl_xor_sync(0xffffffffu, ss, o);
    int warp = threadIdx.x >> 5, lane = threadIdx.x & 31;
    if (lane == 0) sbuf[warp] = ss;
    __syncthreads();
    if (threadIdx.x == 0) {
        float t = 0.f;
#pragma unroll
        for (int i = 0; i < 8; i++) t += sbuf[i];
        sbuf[0] = rsqrtf(t / (float)L + EPSc);
    }
    __syncthreads();
    float sc = sbuf[0];
    for (int i = threadIdx.x; i < L; i += 256) xr[i] = xr[i] * sc * w[i];
}

// ---------------- kv split: rmsnorm(latent) + rope(k_pe) -> kfull ----------------
__global__ __launch_bounds__(256) void kvprep_kernel(
    const float* __restrict__ kv, const float* __restrict__ w,
    const float* __restrict__ fcos, const float* __restrict__ fsin,
    float* __restrict__ kfull)
{
    __shared__ float sbuf[8];
    int row = blockIdx.x;
    int s = row & (Ss - 1);
    const float* kr = kv + (size_t)row * DF;
    float* kf = kfull + (size_t)row * DF;

    float ss = 0.f;
    for (int i = threadIdx.x; i < KVLORA; i += 256) { float v = kr[i]; ss += v * v; }
#pragma unroll
    for (int o = 16; o; o >>= 1) ss += __shfl_xor_sync(0xffffffffu, ss, o);
    int warp = threadIdx.x >> 5, lane = threadIdx.x & 31;
    if (lane == 0) sbuf[warp] = ss;
    __syncthreads();
    if (threadIdx.x == 0) {
        float t = 0.f;
#pragma unroll
        for (int i = 0; i < 8; i++) t += sbuf[i];
        sbuf[0] = rsqrtf(t / (float)KVLORA + EPSc);
    }
    __syncthreads();
    float sc = sbuf[0];
    for (int i = threadIdx.x; i < KVLORA; i += 256) kf[i] = kr[i] * sc * w[i];

    if (threadIdx.x < 32) {
        int i = threadIdx.x;
        float x0 = kr[KVLORA + 2 * i], x1 = kr[KVLORA + 2 * i + 1];
        float c = fcos[s * 32 + i], sn = fsin[s * 32 + i];
        kf[KVLORA + 2 * i]     = x0 * c - x1 * sn;
        kf[KVLORA + 2 * i + 1] = x0 * sn + x1 * c;
    }
}

// ---------------- rope(q_pe) -> qfull[:, :, 512:576] ----------------
__global__ __launch_bounds__(512) void ropeq_kernel(
    const float* __restrict__ q, const float* __restrict__ fcos,
    const float* __restrict__ fsin, float* __restrict__ qfull)
{
    int row = blockIdx.x;
    int s = row & (Ss - 1);
    int t = threadIdx.x;       // 512 = 16 heads * 32 pairs
    int h = t >> 5, i = t & 31;
    const float* qr = q + (size_t)row * (Hh * QKH) + h * QKH + NOPEc;
    float x0 = qr[2 * i], x1 = qr[2 * i + 1];
    float c = fcos[s * 32 + i], sn = fsin[s * 32 + i];
    float* dst = qfull + ((size_t)row * Hh + h) * DF + KVLORA;
    dst[2 * i]     = x0 * c - x1 * sn;
    dst[2 * i + 1] = x0 * sn + x1 * c;
}

// ---------------- flash attention (32q x 32k tiles, fp32) ----------------
#define KSTR 577
#define ATTN_SMEM_BYTES ((64 * KSTR + 32 * 33 + 64) * 4)

__global__ __launch_bounds__(256, 1) void attn_kernel(
    const float* __restrict__ qfull, const float* __restrict__ kfull,
    float* __restrict__ ctx)
{
    extern __shared__ float sm[];
    float* Qs   = sm;                 // 32 x 577
    float* Ks   = sm + 32 * KSTR;     // 32 x 577
    float* Ps   = Ks + 32 * KSTR;     // 32 x 33
    float* arow = Ps + 32 * 33;       // 32
    float* lrow = arow + 32;          // 32

    int tid = threadIdx.x;
    int lane = tid & 31, warp = tid >> 5;
    int rg = tid >> 6, cg = tid & 63;        // O-tile: rows rg*8.., cols cg + 64*vv
    int bh = blockIdx.y;
    int b = bh >> 4, h = bh & 15;
    int s0 = blockIdx.x * 32;

    // load Q tile once
    for (int idx = tid; idx < 32 * DF; idx += 256) {
        int i = idx / DF, d = idx - i * DF;
        Qs[i * KSTR + d] = qfull[((size_t)(b * Ss + s0 + i) * Hh + h) * DF + d];
    }

    float acc[8][8];
#pragma unroll
    for (int i = 0; i < 8; i++)
#pragma unroll
        for (int j = 0; j < 8; j++) acc[i][j] = 0.f;

    float mreg[4], lreg[4];
#pragma unroll
    for (int ii = 0; ii < 4; ii++) { mreg[ii] = -INFINITY; lreg[ii] = 0.f; }

    int ntiles = s0 / 32 + 1;
    for (int kt = 0; kt < ntiles; kt++) {
        int t0 = kt * 32;
        // load K tile
        for (int idx = tid; idx < 32 * DF; idx += 256) {
            int j = idx / DF, d = idx - j * DF;
            Ks[j * KSTR + d] = kfull[(size_t)(b * Ss + t0 + j) * DF + d];
        }
        __syncthreads();

        // ---- scores: warp owns rows 4*warp..4*warp+3, lane = key j ----
        {
            const float* kp = Ks + lane * KSTR;
            const float* q0 = Qs + (warp * 4 + 0) * KSTR;
            const float* q1 = q0 + KSTR;
            const float* q2 = q1 + KSTR;
            const float* q3 = q2 + KSTR;
            float sA = 0.f, sB = 0.f, sC = 0.f, sD = 0.f;
#pragma unroll 4
            for (int k = 0; k < DF; k++) {
                float kv = kp[k];
                sA = fmaf(q0[k], kv, sA);
                sB = fmaf(q1[k], kv, sB);
                sC = fmaf(q2[k], kv, sC);
                sD = fmaf(q3[k], kv, sD);
            }
            float scv[4] = {sA, sB, sC, sD};
#pragma unroll
            for (int ii = 0; ii < 4; ii++) {
                int i = warp * 4 + ii;
                float v = scv[ii] * SCALEc;
                if (t0 + lane > s0 + i) v = -INFINITY;   // causal mask
                float mx = v;
#pragma unroll
                for (int o = 16; o; o >>= 1) mx = fmaxf(mx, __shfl_xor_sync(0xffffffffu, mx, o));
                float mnew = fmaxf(mreg[ii], mx);
                float p = __expf(v - mnew);
                float psum = p;
#pragma unroll
                for (int o = 16; o; o >>= 1) psum += __shfl_xor_sync(0xffffffffu, psum, o);
                float al = __expf(mreg[ii] - mnew);
                lreg[ii] = lreg[ii] * al + psum;
                mreg[ii] = mnew;
                Ps[i * 33 + lane] = p;
                if (lane == 0) arow[i] = al;
            }
        }
        __syncthreads();

        // ---- O update: acc = alpha*acc + P @ V (V = Ks[:, :512]) ----
        {
            float al[8];
#pragma unroll
            for (int ii = 0; ii < 8; ii++) al[ii] = arow[rg * 8 + ii];
#pragma unroll
            for (int ii = 0; ii < 8; ii++)
#pragma unroll
                for (int vv = 0; vv < 8; vv++) acc[ii][vv] *= al[ii];

            for (int j = 0; j < 32; j++) {
                float v[8], p[8];
#pragma unroll
                for (int vv = 0; vv < 8; vv++) v[vv] = Ks[j * KSTR + cg + vv * 64];
#pragma unroll
                for (int ii = 0; ii < 8; ii++) p[ii] = Ps[(rg * 8 + ii) * 33 + j];
#pragma unroll
                for (int ii = 0; ii < 8; ii++)
#pragma unroll
                    for (int vv = 0; vv < 8; vv++)
                        acc[ii][vv] = fmaf(p[ii], v[vv], acc[ii][vv]);
            }
        }
        __syncthreads();
    }

    // publish l, normalize, store ctx
    if (lane == 0) {
#pragma unroll
        for (int ii = 0; ii < 4; ii++) lrow[warp * 4 + ii] = lreg[ii];
    }
    __syncthreads();
#pragma unroll
    for (int ii = 0; ii < 8; ii++) {
        int i = rg * 8 + ii;
        float inv = 1.0f / lrow[i];
        float* cp = ctx + ((size_t)(b * Ss + s0 + i) * Hh + h) * KVLORA + cg;
#pragma unroll
        for (int vv = 0; vv < 8; vv++) cp[vv * 64] = acc[ii][vv] * inv;
    }
}

// ---------------- launch ----------------
extern "C" void kernel_launch(void* const* d_in, const int* in_sizes, int n_in,
                              void* d_out, int out_size)
{
    const float* x     = (const float*)d_in[0];
    const float* fcos  = (const float*)d_in[1];
    const float* fsin  = (const float*)d_in[2];
    // d_in[3] = mask (causal; handled analytically)
    const float* wq_a  = (const float*)d_in[4];
    const float* q_ln  = (const float*)d_in[5];
    const float* wq_b  = (const float*)d_in[6];
    const float* wkv_a = (const float*)d_in[7];
    const float* kv_ln = (const float*)d_in[8];
    const float* wkv_b = (const float*)d_in[9];
    const float* wo    = (const float*)d_in[10];
    float* out = (float*)d_out;

    float *qlat, *q, *kv, *kfull, *qfull, *ctx, *attnout;
    cudaGetSymbolAddress((void**)&qlat,    g_qlat);
    cudaGetSymbolAddress((void**)&q,       g_q);
    cudaGetSymbolAddress((void**)&kv,      g_kv);
    cudaGetSymbolAddress((void**)&kfull,   g_kfull);
    cudaGetSymbolAddress((void**)&qfull,   g_qfull);
    cudaGetSymbolAddress((void**)&ctx,     g_ctx);
    cudaGetSymbolAddress((void**)&attnout, g_attnout);

    dim3 blk(256);

    // 1. q_lat_pre = x @ wq_a^T      (4096 x 1536, K=2048)
    gemm_kernel<true><<<dim3(QLORA / GBN, ROWS / GBM, 1), blk>>>(
        x, DIMc, 0, wq_a, DIMc, 0, qlat, QLORA, 0, ROWS, QLORA, DIMc);

    // 2. rmsnorm in place
    rmsnorm_kernel<<<ROWS, 256>>>(qlat, q_ln, QLORA);

    // 3. q = q_lat @ wq_b^T          (4096 x 3072, K=1536)
    gemm_kernel<true><<<dim3((Hh * QKH) / GBN, ROWS / GBM, 1), blk>>>(
        qlat, QLORA, 0, wq_b, QLORA, 0, q, Hh * QKH, 0, ROWS, Hh * QKH, QLORA);

    // 4. kv = x @ wkv_a^T            (4096 x 576, K=2048)
    gemm_kernel<true><<<dim3((DF + GBN - 1) / GBN, ROWS / GBM, 1), blk>>>(
        x, DIMc, 0, wkv_a, DIMc, 0, kv, DF, 0, ROWS, DF, DIMc);

    // 5. kfull = [rmsnorm(kv_lat), rope(k_pe)]
    kvprep_kernel<<<ROWS, 256>>>(kv, kv_ln, fcos, fsin, kfull);

    // 6. q-absorb per head: qfull[:, h, :512] = q_nope_h @ wkv_b3[h, :128, :]  (NN, batched over 16 heads)
    gemm_kernel<false><<<dim3(KVLORA / GBN, ROWS / GBM, Hh), blk>>>(
        q, Hh * QKH, QKH,
        wkv_b, KVLORA, (long)(NOPEc + VDIMc) * KVLORA,
        qfull, Hh * DF, DF,
        ROWS, KVLORA, NOPEc);

    // 7. qfull[:, h, 512:576] = rope(q_pe)
    ropeq_kernel<<<ROWS, 512>>>(q, fcos, fsin, qfull);

    // 8. flash attention -> ctx (B,S,H,512)
    cudaFuncSetAttribute(attn_kernel, cudaFuncAttributeMaxDynamicSharedMemorySize,
                         ATTN_SMEM_BYTES);
    attn_kernel<<<dim3(Ss / 32, Bb * Hh), 256, ATTN_SMEM_BYTES>>>(qfull, kfull, ctx);

    // 9. per-head out-proj: attnout[:, h*128:(h+1)*128] = ctx_h @ wkv_b3[h, 128:256, :]^T (TN, batched)
    gemm_kernel<true><<<dim3(VDIMc / GBN + (VDIMc % GBN != 0), ROWS / GBM, Hh), blk>>>(
        ctx, Hh * KVLORA, KVLORA,
        wkv_b + (size_t)NOPEc * KVLORA, KVLORA, (long)(NOPEc + VDIMc) * KVLORA,
        attnout, DIMc, VDIMc,
        ROWS, VDIMc, KVLORA);

    // 10. out = attnout @ wo^T       (4096 x 2048, K=2048)
    gemm_kernel<true><<<dim3(DIMc / GBN, ROWS / GBM, 1), blk>>>(
        attnout, DIMc, 0, wo, DIMc, 0, out, DIMc, 0, ROWS, DIMc, DIMc);
}

// round 5
// speedup vs baseline: 1.7322x; 1.7322x over previous
#include <cuda_runtime.h>
#include <math.h>
#include <stdint.h>

// ---------------- problem constants ----------------
#define Bb     2
#define Ss     2048
#define DIMc   2048
#define Hh     16
#define QLORA  1536
#define KVLORA 512
#define NOPEc  128
#define ROPEc  64
#define VDIMc  128
#define QKH    192            // NOPE + ROPE
#define ROWS   (Bb*Ss)        // 4096
#define DF     576            // 512 latent + 64 rope
#define SCALEc 0.07216878364870322f  // 1/sqrt(192)
#define EPSc   1e-6f

// ---------------- scratch (static device arrays; no allocation) ----------------
__device__ float g_qlat[(size_t)ROWS * QLORA];          // 4096 x 1536
__device__ float g_q[(size_t)ROWS * (Hh * QKH)];        // 4096 x 3072
__device__ float g_kv[(size_t)ROWS * DF];               // 4096 x 576
__device__ float g_kfull[(size_t)ROWS * DF];            // 4096 x 576
__device__ float g_qfull[(size_t)ROWS * Hh * DF];       // 4096 x 16 x 576
__device__ float g_ctx[(size_t)ROWS * Hh * KVLORA];     // 4096 x 16 x 512
__device__ float g_attnout[(size_t)ROWS * DIMc];        // 4096 x 2048

// ================= tf32 tensor-core GEMM =================
// C[M,N] = A[M,K] @ op(B). TB=true: B is [N,K] row-major (C = A B^T).
//                          TB=false: B is [K,N] row-major (C = A B).
// Batched over grid.z with element strides sA/sB/sC.
// 128x128 block tile, BK=16, 256 threads (8 warps, 2x4), warp tile 64x32.
// Smem holds tiles PRE-PERMUTED into m16n8k8 fragment order:
//   A: [kstep(2)][mtile(8)][lane(32)][reg(4)]  -> frag load = 1x LDS.128
//   B: [kstep(2)][ntile(16)][lane(32)][reg(2)] -> frag load = 1x LDS.64

__device__ __forceinline__ uint32_t f2tf(float x) {
    uint32_t r;
    asm("cvt.rna.tf32.f32 %0, %1;" : "=r"(r) : "f"(x));
    return r;
}

__device__ __forceinline__ void mma_tf32(float* d, const uint32_t* a, const uint32_t* b) {
    asm volatile(
        "mma.sync.aligned.m16n8k8.row.col.f32.tf32.tf32.f32 "
        "{%0,%1,%2,%3}, {%4,%5,%6,%7}, {%8,%9}, {%0,%1,%2,%3};"
        : "+f"(d[0]), "+f"(d[1]), "+f"(d[2]), "+f"(d[3])
        : "r"(a[0]), "r"(a[1]), "r"(a[2]), "r"(a[3]), "r"(b[0]), "r"(b[1]));
}

template<bool TB>
__global__ __launch_bounds__(256) void gemm_tc_kernel(
    const float* __restrict__ A, int lda, long sA_,
    const float* __restrict__ B, int ldb, long sB_,
    float* __restrict__ C, int ldc, long sC_,
    int M, int N, int K)
{
    __shared__ uint32_t sA[2][2048];   // 2 bufs x (2 ksteps x 8 mtiles x 32 lanes x 4 regs)
    __shared__ uint32_t sB[2][2048];   // 2 bufs x (2 ksteps x 16 ntiles x 32 lanes x 2 regs)

    int z = blockIdx.z;
    A += (size_t)z * sA_;
    B += (size_t)z * sB_;
    C += (size_t)z * sC_;

    const int tid   = threadIdx.x;
    const int lane  = tid & 31;
    const int warp  = tid >> 5;
    const int warp_m = warp >> 2;      // 0..1
    const int warp_n = warp & 3;       // 0..3
    const int m0 = blockIdx.y * 128;
    const int n0 = blockIdx.x * 128;
    const int KT = K >> 4;             // k-tiles of 16

    float acc[4][4][4];
#pragma unroll
    for (int mt = 0; mt < 4; mt++)
#pragma unroll
        for (int nt = 0; nt < 4; nt++)
#pragma unroll
            for (int e = 0; e < 4; e++) acc[mt][nt][e] = 0.f;

    float4 av[2], bv[2];

    // ---- tile load (global -> regs) ----
    auto loadT = [&](int kt) {
        int k0 = kt << 4;
#pragma unroll
        for (int i = 0; i < 2; i++) {
            int s = tid + i * 256;
            { // A slot: m = s>>2, kc = (s&3)*4
                int m = s >> 2, kc = (s & 3) << 2;
                av[i] = *(const float4*)(A + (size_t)(m0 + m) * lda + k0 + kc);
            }
            if (TB) { // B [N,K]: n = s>>2, kc = (s&3)*4
                int n = s >> 2, kc = (s & 3) << 2;
                float4 v = make_float4(0.f, 0.f, 0.f, 0.f);
                if (n0 + n < N) v = *(const float4*)(B + (size_t)(n0 + n) * ldb + k0 + kc);
                bv[i] = v;
            } else {  // B [K,N]: k = s>>5, nc = (s&31)*4
                int k = s >> 5, nc = (s & 31) << 2;
                float4 v = make_float4(0.f, 0.f, 0.f, 0.f);
                if (n0 + nc < N) v = *(const float4*)(B + (size_t)(k0 + k) * ldb + n0 + nc);
                bv[i] = v;
            }
        }
    };

    // ---- tile store (regs -> permuted smem, with tf32 convert) ----
    auto storeT = [&](int buf) {
#pragma unroll
        for (int i = 0; i < 2; i++) {
            int s = tid + i * 256;
            { // A
                int m = s >> 2, kc = (s & 3) << 2;
                int mt = m >> 4, r = m & 15;
                int kstep = kc >> 3;
                int rhalf = (kc & 4) ? 2 : 0;
                uint32_t base = ((kstep * 8 + mt) * 32 + ((r & 7) << 2)) * 4 + ((r >> 3) | rhalf);
                const float* pv = (const float*)&av[i];
#pragma unroll
                for (int e = 0; e < 4; e++)
                    sA[buf][base + e * 4] = f2tf(pv[e]);
            }
            if (TB) {
                int n = s >> 2, kc = (s & 3) << 2;
                int ntile = n >> 3, c = n & 7;
                int kstep = kc >> 3;
                int reg = (kc & 4) ? 1 : 0;
                uint32_t base = ((kstep * 16 + ntile) * 32 + (c << 2)) * 2 + reg;
                const float* pv = (const float*)&bv[i];
#pragma unroll
                for (int e = 0; e < 4; e++)
                    sB[buf][base + e * 2] = f2tf(pv[e]);
            } else {
                int k = s >> 5, nc = (s & 31) << 2;
                int kstep = k >> 3, kk = k & 7;
                int reg = kk >> 2;
                const float* pv = (const float*)&bv[i];
#pragma unroll
                for (int e = 0; e < 4; e++) {
                    int n = nc + e;
                    uint32_t idx = ((kstep * 16 + (n >> 3)) * 32 + ((n & 7) << 2) + (kk & 3)) * 2 + reg;
                    sB[buf][idx] = f2tf(pv[e]);
                }
            }
        }
    };

    auto compute = [&](int buf) {
#pragma unroll
        for (int ks = 0; ks < 2; ks++) {
            uint4 A4[4];
            uint2 B2[4];
#pragma unroll
            for (int mt = 0; mt < 4; mt++)
                A4[mt] = *(const uint4*)&sA[buf][((ks * 8 + warp_m * 4 + mt) * 32 + lane) * 4];
#pragma unroll
            for (int nt = 0; nt < 4; nt++)
                B2[nt] = *(const uint2*)&sB[buf][((ks * 16 + warp_n * 4 + nt) * 32 + lane) * 2];
#pragma unroll
            for (int mt = 0; mt < 4; mt++)
#pragma unroll
                for (int nt = 0; nt < 4; nt++)
                    mma_tf32(acc[mt][nt], (const uint32_t*)&A4[mt], (const uint32_t*)&B2[nt]);
        }
    };

    // mainloop: compute(cur); store(next)->other; sync; prefetch(kt+2)
    loadT(0);
    storeT(0);
    __syncthreads();
    if (KT > 1) loadT(1);

    for (int kt = 0; kt < KT; kt++) {
        int cur = kt & 1;
        compute(cur);
        if (kt + 1 < KT) storeT(1 - cur);
        __syncthreads();
        if (kt + 2 < KT) loadT(kt + 2);
    }

    // ---- epilogue ----
    const int g = lane >> 2, t = lane & 3;
#pragma unroll
    for (int mt = 0; mt < 4; mt++) {
        int row0 = m0 + warp_m * 64 + mt * 16 + g;
#pragma unroll
        for (int nt = 0; nt < 4; nt++) {
            int col = n0 + warp_n * 32 + nt * 8 + 2 * t;
            if (col < N) {
                *(float2*)(C + (size_t)row0 * ldc + col) =
                    make_float2(acc[mt][nt][0], acc[mt][nt][1]);
                *(float2*)(C + (size_t)(row0 + 8) * ldc + col) =
                    make_float2(acc[mt][nt][2], acc[mt][nt][3]);
            }
        }
    }
}

// ---------------- RMSNorm (in-place, one block per row) ----------------
__global__ __launch_bounds__(256) void rmsnorm_kernel(
    float* __restrict__ x, const float* __restrict__ w, int L)
{
    __shared__ float sbuf[8];
    int row = blockIdx.x;
    float* xr = x + (size_t)row * L;
    float ss = 0.f;
    for (int i = threadIdx.x; i < L; i += 256) { float v = xr[i]; ss += v * v; }
#pragma unroll
    for (int o = 16; o; o >>= 1) ss += __shfl_xor_sync(0xffffffffu, ss, o);
    int warp = threadIdx.x >> 5, lane = threadIdx.x & 31;
    if (lane == 0) sbuf[warp] = ss;
    __syncthreads();
    if (threadIdx.x == 0) {
        float t = 0.f;
#pragma unroll
        for (int i = 0; i < 8; i++) t += sbuf[i];
        sbuf[0] = rsqrtf(t / (float)L + EPSc);
    }
    __syncthreads();
    float sc = sbuf[0];
    for (int i = threadIdx.x; i < L; i += 256) xr[i] = xr[i] * sc * w[i];
}

// ---------------- kv split: rmsnorm(latent) + rope(k_pe) -> kfull ----------------
__global__ __launch_bounds__(256) void kvprep_kernel(
    const float* __restrict__ kv, const float* __restrict__ w,
    const float* __restrict__ fcos, const float* __restrict__ fsin,
    float* __restrict__ kfull)
{
    __shared__ float sbuf[8];
    int row = blockIdx.x;
    int s = row & (Ss - 1);
    const float* kr = kv + (size_t)row * DF;
    float* kf = kfull + (size_t)row * DF;

    float ss = 0.f;
    for (int i = threadIdx.x; i < KVLORA; i += 256) { float v = kr[i]; ss += v * v; }
#pragma unroll
    for (int o = 16; o; o >>= 1) ss += __shfl_xor_sync(0xffffffffu, ss, o);
    int warp = threadIdx.x >> 5, lane = threadIdx.x & 31;
    if (lane == 0) sbuf[warp] = ss;
    __syncthreads();
    if (threadIdx.x == 0) {
        float t = 0.f;
#pragma unroll
        for (int i = 0; i < 8; i++) t += sbuf[i];
        sbuf[0] = rsqrtf(t / (float)KVLORA + EPSc);
    }
    __syncthreads();
    float sc = sbuf[0];
    for (int i = threadIdx.x; i < KVLORA; i += 256) kf[i] = kr[i] * sc * w[i];

    if (threadIdx.x < 32) {
        int i = threadIdx.x;
        float x0 = kr[KVLORA + 2 * i], x1 = kr[KVLORA + 2 * i + 1];
        float c = fcos[s * 32 + i], sn = fsin[s * 32 + i];
        kf[KVLORA + 2 * i]     = x0 * c - x1 * sn;
        kf[KVLORA + 2 * i + 1] = x0 * sn + x1 * c;
    }
}

// ---------------- rope(q_pe) -> qfull[:, :, 512:576] ----------------
__global__ __launch_bounds__(512) void ropeq_kernel(
    const float* __restrict__ q, const float* __restrict__ fcos,
    const float* __restrict__ fsin, float* __restrict__ qfull)
{
    int row = blockIdx.x;
    int s = row & (Ss - 1);
    int t = threadIdx.x;       // 512 = 16 heads * 32 pairs
    int h = t >> 5, i = t & 31;
    const float* qr = q + (size_t)row * (Hh * QKH) + h * QKH + NOPEc;
    float x0 = qr[2 * i], x1 = qr[2 * i + 1];
    float c = fcos[s * 32 + i], sn = fsin[s * 32 + i];
    float* dst = qfull + ((size_t)row * Hh + h) * DF + KVLORA;
    dst[2 * i]     = x0 * c - x1 * sn;
    dst[2 * i + 1] = x0 * sn + x1 * c;
}

// ---------------- flash attention (32q x 32k tiles, fp32, vectorized) ----------------
#define KSTR 580   // multiple of 4; float4-aligned rows, conflict-free column reads
#define PSTR 36
#define ATTN_SMEM_BYTES ((64 * KSTR + 32 * PSTR + 64) * 4)

__global__ __launch_bounds__(256, 1) void attn_kernel(
    const float* __restrict__ qfull, const float* __restrict__ kfull,
    float* __restrict__ ctx)
{
    extern __shared__ float sm[];
    float* Qs   = sm;                  // 32 x 580
    float* Ks   = sm + 32 * KSTR;      // 32 x 580
    float* Ps   = Ks + 32 * KSTR;      // 32 x 36
    float* arow = Ps + 32 * PSTR;      // 32
    float* lrow = arow + 32;           // 32

    const int tid = threadIdx.x;
    const int lane = tid & 31, warp = tid >> 5;
    const int rg = tid >> 6;           // 0..3: owns rows rg*8..rg*8+7 in PV
    const int cg = tid & 63;           // owns cols cg*8..cg*8+7 (512 V cols)
    const int bh = blockIdx.y;
    const int b = bh >> 4, h = bh & 15;
    const int s0 = blockIdx.x * 32;

    // load Q tile (float4 copy): 8 threads per row, 18 float4 each
    {
        int qrow = tid >> 3, t8 = tid & 7;
        const float4* src = (const float4*)(qfull + ((size_t)(b * Ss + s0 + qrow) * Hh + h) * DF);
        float4* dst = (float4*)(Qs + qrow * KSTR);
#pragma unroll
        for (int c = 0; c < 18; c++) dst[t8 + c * 8] = src[t8 + c * 8];
    }

    float acc[8][8];
#pragma unroll
    for (int i = 0; i < 8; i++)
#pragma unroll
        for (int j = 0; j < 8; j++) acc[i][j] = 0.f;

    float mreg[4], lreg[4];
#pragma unroll
    for (int ii = 0; ii < 4; ii++) { mreg[ii] = -INFINITY; lreg[ii] = 0.f; }

    const int ntiles = s0 / 32 + 1;
    for (int kt = 0; kt < ntiles; kt++) {
        int t0 = kt * 32;
        // load K tile
        {
            int krow = tid >> 3, t8 = tid & 7;
            const float4* src = (const float4*)(kfull + (size_t)(b * Ss + t0 + krow) * DF);
            float4* dst = (float4*)(Ks + krow * KSTR);
#pragma unroll
            for (int c = 0; c < 18; c++) dst[t8 + c * 8] = src[t8 + c * 8];
        }
        __syncthreads();

        // ---- scores: warp owns rows 4*warp..4*warp+3, lane = key j ----
        {
            const float4* kp = (const float4*)(Ks + lane * KSTR);
            const float4* q0 = (const float4*)(Qs + (warp * 4 + 0) * KSTR);
            const float4* q1 = (const float4*)(Qs + (warp * 4 + 1) * KSTR);
            const float4* q2 = (const float4*)(Qs + (warp * 4 + 2) * KSTR);
            const float4* q3 = (const float4*)(Qs + (warp * 4 + 3) * KSTR);
            float sA = 0.f, sB = 0.f, sC = 0.f, sD = 0.f;
#pragma unroll 4
            for (int k4 = 0; k4 < DF / 4; k4++) {
                float4 kv = kp[k4];
                float4 v0 = q0[k4];
                sA = fmaf(v0.x, kv.x, sA); sA = fmaf(v0.y, kv.y, sA);
                sA = fmaf(v0.z, kv.z, sA); sA = fmaf(v0.w, kv.w, sA);
                float4 v1 = q1[k4];
                sB = fmaf(v1.x, kv.x, sB); sB = fmaf(v1.y, kv.y, sB);
                sB = fmaf(v1.z, kv.z, sB); sB = fmaf(v1.w, kv.w, sB);
                float4 v2 = q2[k4];
                sC = fmaf(v2.x, kv.x, sC); sC = fmaf(v2.y, kv.y, sC);
                sC = fmaf(v2.z, kv.z, sC); sC = fmaf(v2.w, kv.w, sC);
                float4 v3 = q3[k4];
                sD = fmaf(v3.x, kv.x, sD); sD = fmaf(v3.y, kv.y, sD);
                sD = fmaf(v3.z, kv.z, sD); sD = fmaf(v3.w, kv.w, sD);
            }
            float scv[4] = {sA, sB, sC, sD};
#pragma unroll
            for (int ii = 0; ii < 4; ii++) {
                int i = warp * 4 + ii;
                float v = scv[ii] * SCALEc;
                if (t0 + lane > s0 + i) v = -INFINITY;   // causal mask
                float mx = v;
#pragma unroll
                for (int o = 16; o; o >>= 1) mx = fmaxf(mx, __shfl_xor_sync(0xffffffffu, mx, o));
                float mnew = fmaxf(mreg[ii], mx);
                float p = __expf(v - mnew);
                float psum = p;
#pragma unroll
                for (int o = 16; o; o >>= 1) psum += __shfl_xor_sync(0xffffffffu, psum, o);
                float al = __expf(mreg[ii] - mnew);
                lreg[ii] = lreg[ii] * al + psum;
                mreg[ii] = mnew;
                Ps[i * PSTR + lane] = p;
                if (lane == 0) arow[i] = al;
            }
        }
        __syncthreads();

        // ---- O update: acc = alpha*acc + P @ V (V = Ks[:, :512]) ----
        {
#pragma unroll
            for (int ii = 0; ii < 8; ii++) {
                float al = arow[rg * 8 + ii];
#pragma unroll
                for (int vv = 0; vv < 8; vv++) acc[ii][vv] *= al;
            }
            const float* vbase = Ks + cg * 8;
            for (int j0 = 0; j0 < 32; j0 += 4) {
                float4 p4[8];
#pragma unroll
                for (int ii = 0; ii < 8; ii++)
                    p4[ii] = *(const float4*)&Ps[(rg * 8 + ii) * PSTR + j0];
#pragma unroll
                for (int jj = 0; jj < 4; jj++) {
                    const float4* vp = (const float4*)(vbase + (j0 + jj) * KSTR);
                    float4 va = vp[0], vb = vp[1];
                    const float* pp = (const float*)&p4[0] + jj;
#pragma unroll
                    for (int ii = 0; ii < 8; ii++) {
                        float p = pp[ii * 4];
                        acc[ii][0] = fmaf(p, va.x, acc[ii][0]);
                        acc[ii][1] = fmaf(p, va.y, acc[ii][1]);
                        acc[ii][2] = fmaf(p, va.z, acc[ii][2]);
                        acc[ii][3] = fmaf(p, va.w, acc[ii][3]);
                        acc[ii][4] = fmaf(p, vb.x, acc[ii][4]);
                        acc[ii][5] = fmaf(p, vb.y, acc[ii][5]);
                        acc[ii][6] = fmaf(p, vb.z, acc[ii][6]);
                        acc[ii][7] = fmaf(p, vb.w, acc[ii][7]);
                    }
                }
            }
        }
        __syncthreads();
    }

    // publish l, normalize, store ctx (contiguous float4 x2 per row)
    if (lane == 0) {
#pragma unroll
        for (int ii = 0; ii < 4; ii++) lrow[warp * 4 + ii] = lreg[ii];
    }
    __syncthreads();
#pragma unroll
    for (int ii = 0; ii < 8; ii++) {
        int i = rg * 8 + ii;
        float inv = 1.0f / lrow[i];
        float* cp = ctx + ((size_t)(b * Ss + s0 + i) * Hh + h) * KVLORA + cg * 8;
        float4 o0 = make_float4(acc[ii][0] * inv, acc[ii][1] * inv, acc[ii][2] * inv, acc[ii][3] * inv);
        float4 o1 = make_float4(acc[ii][4] * inv, acc[ii][5] * inv, acc[ii][6] * inv, acc[ii][7] * inv);
        *(float4*)cp = o0;
        *(float4*)(cp + 4) = o1;
    }
}

// ---------------- launch ----------------
extern "C" void kernel_launch(void* const* d_in, const int* in_sizes, int n_in,
                              void* d_out, int out_size)
{
    const float* x     = (const float*)d_in[0];
    const float* fcos  = (const float*)d_in[1];
    const float* fsin  = (const float*)d_in[2];
    // d_in[3] = mask (causal; handled analytically)
    const float* wq_a  = (const float*)d_in[4];
    const float* q_ln  = (const float*)d_in[5];
    const float* wq_b  = (const float*)d_in[6];
    const float* wkv_a = (const float*)d_in[7];
    const float* kv_ln = (const float*)d_in[8];
    const float* wkv_b = (const float*)d_in[9];
    const float* wo    = (const float*)d_in[10];
    float* out = (float*)d_out;

    float *qlat, *q, *kv, *kfull, *qfull, *ctx, *attnout;
    cudaGetSymbolAddress((void**)&qlat,    g_qlat);
    cudaGetSymbolAddress((void**)&q,       g_q);
    cudaGetSymbolAddress((void**)&kv,      g_kv);
    cudaGetSymbolAddress((void**)&kfull,   g_kfull);
    cudaGetSymbolAddress((void**)&qfull,   g_qfull);
    cudaGetSymbolAddress((void**)&ctx,     g_ctx);
    cudaGetSymbolAddress((void**)&attnout, g_attnout);

    dim3 blk(256);

    // 1. q_lat_pre = x @ wq_a^T      (4096 x 1536, K=2048)
    gemm_tc_kernel<true><<<dim3(QLORA / 128, ROWS / 128, 1), blk>>>(
        x, DIMc, 0, wq_a, DIMc, 0, qlat, QLORA, 0, ROWS, QLORA, DIMc);

    // 2. rmsnorm in place
    rmsnorm_kernel<<<ROWS, 256>>>(qlat, q_ln, QLORA);

    // 3. q = q_lat @ wq_b^T          (4096 x 3072, K=1536)
    gemm_tc_kernel<true><<<dim3((Hh * QKH) / 128, ROWS / 128, 1), blk>>>(
        qlat, QLORA, 0, wq_b, QLORA, 0, q, Hh * QKH, 0, ROWS, Hh * QKH, QLORA);

    // 4. kv = x @ wkv_a^T            (4096 x 576, K=2048)
    gemm_tc_kernel<true><<<dim3((DF + 127) / 128, ROWS / 128, 1), blk>>>(
        x, DIMc, 0, wkv_a, DIMc, 0, kv, DF, 0, ROWS, DF, DIMc);

    // 5. kfull = [rmsnorm(kv_lat), rope(k_pe)]
    kvprep_kernel<<<ROWS, 256>>>(kv, kv_ln, fcos, fsin, kfull);

    // 6. q-absorb per head: qfull[:, h, :512] = q_nope_h @ wkv_b3[h, :128, :]  (NN, batched over heads)
    gemm_tc_kernel<false><<<dim3(KVLORA / 128, ROWS / 128, Hh), blk>>>(
        q, Hh * QKH, QKH,
        wkv_b, KVLORA, (long)(NOPEc + VDIMc) * KVLORA,
        qfull, Hh * DF, DF,
        ROWS, KVLORA, NOPEc);

    // 7. qfull[:, h, 512:576] = rope(q_pe)
    ropeq_kernel<<<ROWS, 512>>>(q, fcos, fsin, qfull);

    // 8. flash attention -> ctx (B,S,H,512)
    cudaFuncSetAttribute(attn_kernel, cudaFuncAttributeMaxDynamicSharedMemorySize,
                         ATTN_SMEM_BYTES);
    attn_kernel<<<dim3(Ss / 32, Bb * Hh), 256, ATTN_SMEM_BYTES>>>(qfull, kfull, ctx);

    // 9. per-head out-proj: attnout[:, h*128:(h+1)*128] = ctx_h @ wkv_b3[h, 128:256, :]^T (TN, batched)
    gemm_tc_kernel<true><<<dim3(1, ROWS / 128, Hh), blk>>>(
        ctx, Hh * KVLORA, KVLORA,
        wkv_b + (size_t)NOPEc * KVLORA, KVLORA, (long)(NOPEc + VDIMc) * KVLORA,
        attnout, DIMc, VDIMc,
        ROWS, VDIMc, KVLORA);

    // 10. out = attnout @ wo^T       (4096 x 2048, K=2048)
    gemm_tc_kernel<true><<<dim3(DIMc / 128, ROWS / 128, 1), blk>>>(
        attnout, DIMc, 0, wo, DIMc, 0, out, DIMc, 0, ROWS, DIMc, DIMc);
}

// round 6
// speedup vs baseline: 3.5420x; 2.0448x over previous
#include <cuda_runtime.h>
#include <math.h>
#include <stdint.h>

// ---------------- problem constants ----------------
#define Bb     2
#define Ss     2048
#define DIMc   2048
#define Hh     16
#define QLORA  1536
#define KVLORA 512
#define NOPEc  128
#define ROPEc  64
#define VDIMc  128
#define QKH    192            // NOPE + ROPE
#define ROWS   (Bb*Ss)        // 4096
#define DF     576            // 512 latent + 64 rope
#define SCALEc 0.07216878364870322f  // 1/sqrt(192)
#define EPSc   1e-6f

// ---------------- scratch (static device arrays; no allocation) ----------------
__device__ float g_qlat[(size_t)ROWS * QLORA];          // 4096 x 1536
__device__ float g_q[(size_t)ROWS * (Hh * QKH)];        // 4096 x 3072
__device__ float g_kv[(size_t)ROWS * DF];               // 4096 x 576
__device__ float g_kfull[(size_t)ROWS * DF];            // 4096 x 576
__device__ float g_qfull[(size_t)ROWS * Hh * DF];       // 4096 x 16 x 576
__device__ float g_ctx[(size_t)ROWS * Hh * KVLORA];     // 4096 x 16 x 512
__device__ float g_attnout[(size_t)ROWS * DIMc];        // 4096 x 2048

// ================= tf32 helpers =================
__device__ __forceinline__ uint32_t f2tf(float x) {
    uint32_t r;
    asm("cvt.rna.tf32.f32 %0, %1;" : "=r"(r) : "f"(x));
    return r;
}
__device__ __forceinline__ float4 tf4(float4 v) {
    v.x = __uint_as_float(f2tf(v.x));
    v.y = __uint_as_float(f2tf(v.y));
    v.z = __uint_as_float(f2tf(v.z));
    v.w = __uint_as_float(f2tf(v.w));
    return v;
}
__device__ __forceinline__ void mma_tf32(float* d, const uint32_t* a, const uint32_t* b) {
    asm volatile(
        "mma.sync.aligned.m16n8k8.row.col.f32.tf32.tf32.f32 "
        "{%0,%1,%2,%3}, {%4,%5,%6,%7}, {%8,%9}, {%0,%1,%2,%3};"
        : "+f"(d[0]), "+f"(d[1]), "+f"(d[2]), "+f"(d[3])
        : "r"(a[0]), "r"(a[1]), "r"(a[2]), "r"(a[3]), "r"(b[0]), "r"(b[1]));
}

// ================= tf32 tensor-core GEMM (unchanged from R4) =================
template<bool TB>
__global__ __launch_bounds__(256) void gemm_tc_kernel(
    const float* __restrict__ A, int lda, long sA_,
    const float* __restrict__ B, int ldb, long sB_,
    float* __restrict__ C, int ldc, long sC_,
    int M, int N, int K)
{
    __shared__ uint32_t sA[2][2048];
    __shared__ uint32_t sB[2][2048];

    int z = blockIdx.z;
    A += (size_t)z * sA_;
    B += (size_t)z * sB_;
    C += (size_t)z * sC_;

    const int tid   = threadIdx.x;
    const int lane  = tid & 31;
    const int warp  = tid >> 5;
    const int warp_m = warp >> 2;
    const int warp_n = warp & 3;
    const int m0 = blockIdx.y * 128;
    const int n0 = blockIdx.x * 128;
    const int KT = K >> 4;

    float acc[4][4][4];
#pragma unroll
    for (int mt = 0; mt < 4; mt++)
#pragma unroll
        for (int nt = 0; nt < 4; nt++)
#pragma unroll
            for (int e = 0; e < 4; e++) acc[mt][nt][e] = 0.f;

    float4 av[2], bv[2];

    auto loadT = [&](int kt) {
        int k0 = kt << 4;
#pragma unroll
        for (int i = 0; i < 2; i++) {
            int s = tid + i * 256;
            {
                int m = s >> 2, kc = (s & 3) << 2;
                av[i] = *(const float4*)(A + (size_t)(m0 + m) * lda + k0 + kc);
            }
            if (TB) {
                int n = s >> 2, kc = (s & 3) << 2;
                float4 v = make_float4(0.f, 0.f, 0.f, 0.f);
                if (n0 + n < N) v = *(const float4*)(B + (size_t)(n0 + n) * ldb + k0 + kc);
                bv[i] = v;
            } else {
                int k = s >> 5, nc = (s & 31) << 2;
                float4 v = make_float4(0.f, 0.f, 0.f, 0.f);
                if (n0 + nc < N) v = *(const float4*)(B + (size_t)(k0 + k) * ldb + n0 + nc);
                bv[i] = v;
            }
        }
    };

    auto storeT = [&](int buf) {
#pragma unroll
        for (int i = 0; i < 2; i++) {
            int s = tid + i * 256;
            {
                int m = s >> 2, kc = (s & 3) << 2;
                int mt = m >> 4, r = m & 15;
                int kstep = kc >> 3;
                int rhalf = (kc & 4) ? 2 : 0;
                uint32_t base = ((kstep * 8 + mt) * 32 + ((r & 7) << 2)) * 4 + ((r >> 3) | rhalf);
                const float* pv = (const float*)&av[i];
#pragma unroll
                for (int e = 0; e < 4; e++)
                    sA[buf][base + e * 4] = f2tf(pv[e]);
            }
            if (TB) {
                int n = s >> 2, kc = (s & 3) << 2;
                int ntile = n >> 3, c = n & 7;
                int kstep = kc >> 3;
                int reg = (kc & 4) ? 1 : 0;
                uint32_t base = ((kstep * 16 + ntile) * 32 + (c << 2)) * 2 + reg;
                const float* pv = (const float*)&bv[i];
#pragma unroll
                for (int e = 0; e < 4; e++)
                    sB[buf][base + e * 2] = f2tf(pv[e]);
            } else {
                int k = s >> 5, nc = (s & 31) << 2;
                int kstep = k >> 3, kk = k & 7;
                int reg = kk >> 2;
                const float* pv = (const float*)&bv[i];
#pragma unroll
                for (int e = 0; e < 4; e++) {
                    int n = nc + e;
                    uint32_t idx = ((kstep * 16 + (n >> 3)) * 32 + ((n & 7) << 2) + (kk & 3)) * 2 + reg;
                    sB[buf][idx] = f2tf(pv[e]);
                }
            }
        }
    };

    auto compute = [&](int buf) {
#pragma unroll
        for (int ks = 0; ks < 2; ks++) {
            uint4 A4[4];
            uint2 B2[4];
#pragma unroll
            for (int mt = 0; mt < 4; mt++)
                A4[mt] = *(const uint4*)&sA[buf][((ks * 8 + warp_m * 4 + mt) * 32 + lane) * 4];
#pragma unroll
            for (int nt = 0; nt < 4; nt++)
                B2[nt] = *(const uint2*)&sB[buf][((ks * 16 + warp_n * 4 + nt) * 32 + lane) * 2];
#pragma unroll
            for (int mt = 0; mt < 4; mt++)
#pragma unroll
                for (int nt = 0; nt < 4; nt++)
                    mma_tf32(acc[mt][nt], (const uint32_t*)&A4[mt], (const uint32_t*)&B2[nt]);
        }
    };

    loadT(0);
    storeT(0);
    __syncthreads();
    if (KT > 1) loadT(1);

    for (int kt = 0; kt < KT; kt++) {
        int cur = kt & 1;
        compute(cur);
        if (kt + 1 < KT) storeT(1 - cur);
        __syncthreads();
        if (kt + 2 < KT) loadT(kt + 2);
    }

    const int g = lane >> 2, t = lane & 3;
#pragma unroll
    for (int mt = 0; mt < 4; mt++) {
        int row0 = m0 + warp_m * 64 + mt * 16 + g;
#pragma unroll
        for (int nt = 0; nt < 4; nt++) {
            int col = n0 + warp_n * 32 + nt * 8 + 2 * t;
            if (col < N) {
                *(float2*)(C + (size_t)row0 * ldc + col) =
                    make_float2(acc[mt][nt][0], acc[mt][nt][1]);
                *(float2*)(C + (size_t)(row0 + 8) * ldc + col) =
                    make_float2(acc[mt][nt][2], acc[mt][nt][3]);
            }
        }
    }
}

// ---------------- RMSNorm (in-place, one block per row) ----------------
__global__ __launch_bounds__(256) void rmsnorm_kernel(
    float* __restrict__ x, const float* __restrict__ w, int L)
{
    __shared__ float sbuf[8];
    int row = blockIdx.x;
    float* xr = x + (size_t)row * L;
    float ss = 0.f;
    for (int i = threadIdx.x; i < L; i += 256) { float v = xr[i]; ss += v * v; }
#pragma unroll
    for (int o = 16; o; o >>= 1) ss += __shfl_xor_sync(0xffffffffu, ss, o);
    int warp = threadIdx.x >> 5, lane = threadIdx.x & 31;
    if (lane == 0) sbuf[warp] = ss;
    __syncthreads();
    if (threadIdx.x == 0) {
        float t = 0.f;
#pragma unroll
        for (int i = 0; i < 8; i++) t += sbuf[i];
        sbuf[0] = rsqrtf(t / (float)L + EPSc);
    }
    __syncthreads();
    float sc = sbuf[0];
    for (int i = threadIdx.x; i < L; i += 256) xr[i] = xr[i] * sc * w[i];
}

// ---------------- kv split: rmsnorm(latent) + rope(k_pe) -> kfull ----------------
__global__ __launch_bounds__(256) void kvprep_kernel(
    const float* __restrict__ kv, const float* __restrict__ w,
    const float* __restrict__ fcos, const float* __restrict__ fsin,
    float* __restrict__ kfull)
{
    __shared__ float sbuf[8];
    int row = blockIdx.x;
    int s = row & (Ss - 1);
    const float* kr = kv + (size_t)row * DF;
    float* kf = kfull + (size_t)row * DF;

    float ss = 0.f;
    for (int i = threadIdx.x; i < KVLORA; i += 256) { float v = kr[i]; ss += v * v; }
#pragma unroll
    for (int o = 16; o; o >>= 1) ss += __shfl_xor_sync(0xffffffffu, ss, o);
    int warp = threadIdx.x >> 5, lane = threadIdx.x & 31;
    if (lane == 0) sbuf[warp] = ss;
    __syncthreads();
    if (threadIdx.x == 0) {
        float t = 0.f;
#pragma unroll
        for (int i = 0; i < 8; i++) t += sbuf[i];
        sbuf[0] = rsqrtf(t / (float)KVLORA + EPSc);
    }
    __syncthreads();
    float sc = sbuf[0];
    for (int i = threadIdx.x; i < KVLORA; i += 256) kf[i] = kr[i] * sc * w[i];

    if (threadIdx.x < 32) {
        int i = threadIdx.x;
        float x0 = kr[KVLORA + 2 * i], x1 = kr[KVLORA + 2 * i + 1];
        float c = fcos[s * 32 + i], sn = fsin[s * 32 + i];
        kf[KVLORA + 2 * i]     = x0 * c - x1 * sn;
        kf[KVLORA + 2 * i + 1] = x0 * sn + x1 * c;
    }
}

// ---------------- rope(q_pe) -> qfull[:, :, 512:576] ----------------
__global__ __launch_bounds__(512) void ropeq_kernel(
    const float* __restrict__ q, const float* __restrict__ fcos,
    const float* __restrict__ fsin, float* __restrict__ qfull)
{
    int row = blockIdx.x;
    int s = row & (Ss - 1);
    int t = threadIdx.x;       // 512 = 16 heads * 32 pairs
    int h = t >> 5, i = t & 31;
    const float* qr = q + (size_t)row * (Hh * QKH) + h * QKH + NOPEc;
    float x0 = qr[2 * i], x1 = qr[2 * i + 1];
    float c = fcos[s * 32 + i], sn = fsin[s * 32 + i];
    float* dst = qfull + ((size_t)row * Hh + h) * DF + KVLORA;
    dst[2 * i]     = x0 * c - x1 * sn;
    dst[2 * i + 1] = x0 * sn + x1 * c;
}

// ---------------- flash attention (tf32 tensor core, 32q x 32k tiles) ----------------
// Smem stride 588 (== 12 mod 32): conflict-free for BOTH column-pattern
// fragment loads (s*g + t) and row-pattern V loads (s*t + g).
#define KSTR 588
#define PSTR 36
#define ATTN_SMEM_BYTES ((2 * 32 * KSTR + 2 * 32 * PSTR + 64) * 4)

__global__ __launch_bounds__(256, 1) void attn_kernel(
    const float* __restrict__ qfull, const float* __restrict__ kfull,
    float* __restrict__ ctx)
{
    extern __shared__ float sm[];
    float* Qs   = sm;                   // 32 x 588 (tf32)
    float* Ks   = sm + 32 * KSTR;       // 32 x 588 (tf32; cols 0..511 double as V)
    float* Ps0  = Ks + 32 * KSTR;       // 32 x 36 (score partial wk=0; later P)
    float* Ps1  = Ps0 + 32 * PSTR;      // 32 x 36 (score partial wk=1)
    float* arow = Ps1 + 32 * PSTR;      // 32
    float* lrow = arow + 32;            // 32

    const int tid  = threadIdx.x;
    const int lane = tid & 31, warp = tid >> 5;
    const int g = lane >> 2, t = lane & 3;
    // score roles: 2(m) x 2(n) x 2(k-split)
    const int wk = warp & 1, wn = (warp >> 1) & 1, wm = warp >> 2;
    const int bh = blockIdx.y;
    const int b = bh >> 4, h = bh & 15;
    const int s0 = blockIdx.x * 32;

    // ---- load Q tile (tf32-rounded) ----
    {
        int qrow = tid >> 3, t8 = tid & 7;
        const float4* src = (const float4*)(qfull + ((size_t)(b * Ss + s0 + qrow) * Hh + h) * DF);
        float4* dst = (float4*)(Qs + qrow * KSTR);
#pragma unroll
        for (int c = 0; c < 18; c++) dst[t8 + c * 8] = tf4(src[t8 + c * 8]);
    }

    float oacc[2][8][4];
#pragma unroll
    for (int mt = 0; mt < 2; mt++)
#pragma unroll
        for (int nt = 0; nt < 8; nt++)
#pragma unroll
            for (int e = 0; e < 4; e++) oacc[mt][nt][e] = 0.f;

    float mreg[4], lreg[4];
#pragma unroll
    for (int ii = 0; ii < 4; ii++) { mreg[ii] = -INFINITY; lreg[ii] = 0.f; }

    const int ntiles = s0 / 32 + 1;
    for (int kt = 0; kt < ntiles; kt++) {
        int t0 = kt * 32;
        // ---- load K tile (tf32-rounded) ----
        {
            int krow = tid >> 3, t8 = tid & 7;
            const float4* src = (const float4*)(kfull + (size_t)(b * Ss + t0 + krow) * DF);
            float4* dst = (float4*)(Ks + krow * KSTR);
#pragma unroll
            for (int c = 0; c < 18; c++) dst[t8 + c * 8] = tf4(src[t8 + c * 8]);
        }
        __syncthreads();

        // ---- scores: warp (wm,wn,wk) -> m16 x n16 tile, k-half wk ----
        {
            float sacc[2][4];
#pragma unroll
            for (int nt = 0; nt < 2; nt++)
#pragma unroll
                for (int e = 0; e < 4; e++) sacc[nt][e] = 0.f;

            const float* qb0 = Qs + (wm * 16 + g) * KSTR + wk * 288 + t;
#pragma unroll 4
            for (int ks = 0; ks < 36; ks++) {
                const float* qb = qb0 + ks * 8;
                uint32_t a[4];
                a[0] = __float_as_uint(qb[0]);
                a[1] = __float_as_uint(qb[8 * KSTR]);
                a[2] = __float_as_uint(qb[4]);
                a[3] = __float_as_uint(qb[8 * KSTR + 4]);
#pragma unroll
                for (int nt = 0; nt < 2; nt++) {
                    const float* kb = Ks + (wn * 16 + nt * 8 + g) * KSTR + wk * 288 + ks * 8 + t;
                    uint32_t bf[2];
                    bf[0] = __float_as_uint(kb[0]);
                    bf[1] = __float_as_uint(kb[4]);
                    mma_tf32(sacc[nt], a, bf);
                }
            }
            float* Pw = wk ? Ps1 : Ps0;
#pragma unroll
            for (int nt = 0; nt < 2; nt++) {
                int colb = wn * 16 + nt * 8 + 2 * t;
                *(float2*)&Pw[(wm * 16 + g) * PSTR + colb] =
                    make_float2(sacc[nt][0], sacc[nt][1]);
                *(float2*)&Pw[(wm * 16 + g + 8) * PSTR + colb] =
                    make_float2(sacc[nt][2], sacc[nt][3]);
            }
        }
        __syncthreads();

        // ---- softmax: warp owns rows 4*warp..+3, lane = key j ----
        {
#pragma unroll
            for (int ii = 0; ii < 4; ii++) {
                int i = warp * 4 + ii;
                float v = (Ps0[i * PSTR + lane] + Ps1[i * PSTR + lane]) * SCALEc;
                if (t0 + lane > s0 + i) v = -INFINITY;   // causal mask
                float mx = v;
#pragma unroll
                for (int o = 16; o; o >>= 1) mx = fmaxf(mx, __shfl_xor_sync(0xffffffffu, mx, o));
                float mnew = fmaxf(mreg[ii], mx);
                float p = __expf(v - mnew);
                float psum = p;
#pragma unroll
                for (int o = 16; o; o >>= 1) psum += __shfl_xor_sync(0xffffffffu, psum, o);
                float al = __expf(mreg[ii] - mnew);
                lreg[ii] = lreg[ii] * al + psum;
                mreg[ii] = mnew;
                Ps0[i * PSTR + lane] = __uint_as_float(f2tf(p));
                if (lane == 0) arow[i] = al;
            }
        }
        __syncthreads();

        // ---- PV: warp owns all 32 rows x cols [warp*64, warp*64+64) ----
        {
#pragma unroll
            for (int mt = 0; mt < 2; mt++) {
                float al0 = arow[mt * 16 + g];
                float al1 = arow[mt * 16 + g + 8];
#pragma unroll
                for (int nt = 0; nt < 8; nt++) {
                    oacc[mt][nt][0] *= al0; oacc[mt][nt][1] *= al0;
                    oacc[mt][nt][2] *= al1; oacc[mt][nt][3] *= al1;
                }
            }
#pragma unroll
            for (int jb = 0; jb < 4; jb++) {
                int j0 = jb * 8;
                uint32_t pa[2][4];
#pragma unroll
                for (int mt = 0; mt < 2; mt++) {
                    const float* pb = Ps0 + (mt * 16 + g) * PSTR + j0 + t;
                    pa[mt][0] = __float_as_uint(pb[0]);
                    pa[mt][1] = __float_as_uint(pb[8 * PSTR]);
                    pa[mt][2] = __float_as_uint(pb[4]);
                    pa[mt][3] = __float_as_uint(pb[8 * PSTR + 4]);
                }
#pragma unroll
                for (int nt = 0; nt < 8; nt++) {
                    const float* vbp = Ks + (j0 + t) * KSTR + warp * 64 + nt * 8 + g;
                    uint32_t vb[2];
                    vb[0] = __float_as_uint(vbp[0]);
                    vb[1] = __float_as_uint(vbp[4 * KSTR]);
                    mma_tf32(oacc[0][nt], pa[0], vb);
                    mma_tf32(oacc[1][nt], pa[1], vb);
                }
            }
        }
        __syncthreads();
    }

    // ---- publish l, normalize, store ctx ----
    if (lane == 0) {
#pragma unroll
        for (int ii = 0; ii < 4; ii++) lrow[warp * 4 + ii] = lreg[ii];
    }
    __syncthreads();
#pragma unroll
    for (int mt = 0; mt < 2; mt++) {
        int r0 = mt * 16 + g;
        int r1 = mt * 16 + g + 8;
        float inv0 = 1.0f / lrow[r0];
        float inv1 = 1.0f / lrow[r1];
        float* cp0 = ctx + ((size_t)(b * Ss + s0 + r0) * Hh + h) * KVLORA + warp * 64;
        float* cp1 = ctx + ((size_t)(b * Ss + s0 + r1) * Hh + h) * KVLORA + warp * 64;
#pragma unroll
        for (int nt = 0; nt < 8; nt++) {
            int col = nt * 8 + 2 * t;
            *(float2*)(cp0 + col) = make_float2(oacc[mt][nt][0] * inv0, oacc[mt][nt][1] * inv0);
            *(float2*)(cp1 + col) = make_float2(oacc[mt][nt][2] * inv1, oacc[mt][nt][3] * inv1);
        }
    }
}

// ---------------- launch ----------------
extern "C" void kernel_launch(void* const* d_in, const int* in_sizes, int n_in,
                              void* d_out, int out_size)
{
    const float* x     = (const float*)d_in[0];
    const float* fcos  = (const float*)d_in[1];
    const float* fsin  = (const float*)d_in[2];
    // d_in[3] = mask (causal; handled analytically)
    const float* wq_a  = (const float*)d_in[4];
    const float* q_ln  = (const float*)d_in[5];
    const float* wq_b  = (const float*)d_in[6];
    const float* wkv_a = (const float*)d_in[7];
    const float* kv_ln = (const float*)d_in[8];
    const float* wkv_b = (const float*)d_in[9];
    const float* wo    = (const float*)d_in[10];
    float* out = (float*)d_out;

    float *qlat, *q, *kv, *kfull, *qfull, *ctx, *attnout;
    cudaGetSymbolAddress((void**)&qlat,    g_qlat);
    cudaGetSymbolAddress((void**)&q,       g_q);
    cudaGetSymbolAddress((void**)&kv,      g_kv);
    cudaGetSymbolAddress((void**)&kfull,   g_kfull);
    cudaGetSymbolAddress((void**)&qfull,   g_qfull);
    cudaGetSymbolAddress((void**)&ctx,     g_ctx);
    cudaGetSymbolAddress((void**)&attnout, g_attnout);

    dim3 blk(256);

    // 1. q_lat_pre = x @ wq_a^T      (4096 x 1536, K=2048)
    gemm_tc_kernel<true><<<dim3(QLORA / 128, ROWS / 128, 1), blk>>>(
        x, DIMc, 0, wq_a, DIMc, 0, qlat, QLORA, 0, ROWS, QLORA, DIMc);

    // 2. rmsnorm in place
    rmsnorm_kernel<<<ROWS, 256>>>(qlat, q_ln, QLORA);

    // 3. q = q_lat @ wq_b^T          (4096 x 3072, K=1536)
    gemm_tc_kernel<true><<<dim3((Hh * QKH) / 128, ROWS / 128, 1), blk>>>(
        qlat, QLORA, 0, wq_b, QLORA, 0, q, Hh * QKH, 0, ROWS, Hh * QKH, QLORA);

    // 4. kv = x @ wkv_a^T            (4096 x 576, K=2048)
    gemm_tc_kernel<true><<<dim3((DF + 127) / 128, ROWS / 128, 1), blk>>>(
        x, DIMc, 0, wkv_a, DIMc, 0, kv, DF, 0, ROWS, DF, DIMc);

    // 5. kfull = [rmsnorm(kv_lat), rope(k_pe)]
    kvprep_kernel<<<ROWS, 256>>>(kv, kv_ln, fcos, fsin, kfull);

    // 6. q-absorb per head: qfull[:, h, :512] = q_nope_h @ wkv_b3[h, :128, :]  (NN, batched over heads)
    gemm_tc_kernel<false><<<dim3(KVLORA / 128, ROWS / 128, Hh), blk>>>(
        q, Hh * QKH, QKH,
        wkv_b, KVLORA, (long)(NOPEc + VDIMc) * KVLORA,
        qfull, Hh * DF, DF,
        ROWS, KVLORA, NOPEc);

    // 7. qfull[:, h, 512:576] = rope(q_pe)
    ropeq_kernel<<<ROWS, 512>>>(q, fcos, fsin, qfull);

    // 8. flash attention -> ctx (B,S,H,512), tf32 tensor cores
    cudaFuncSetAttribute(attn_kernel, cudaFuncAttributeMaxDynamicSharedMemorySize,
                         ATTN_SMEM_BYTES);
    attn_kernel<<<dim3(Ss / 32, Bb * Hh), 256, ATTN_SMEM_BYTES>>>(qfull, kfull, ctx);

    // 9. per-head out-proj: attnout[:, h*128:(h+1)*128] = ctx_h @ wkv_b3[h, 128:256, :]^T (TN, batched)
    gemm_tc_kernel<true><<<dim3(1, ROWS / 128, Hh), blk>>>(
        ctx, Hh * KVLORA, KVLORA,
        wkv_b + (size_t)NOPEc * KVLORA, KVLORA, (long)(NOPEc + VDIMc) * KVLORA,
        attnout, DIMc, VDIMc,
        ROWS, VDIMc, KVLORA);

    // 10. out = attnout @ wo^T       (4096 x 2048, K=2048)
    gemm_tc_kernel<true><<<dim3(DIMc / 128, ROWS / 128, 1), blk>>>(
        attnout, DIMc, 0, wo, DIMc, 0, out, DIMc, 0, ROWS, DIMc, DIMc);
}

// round 7
// speedup vs baseline: 4.0486x; 1.1430x over previous
#include <cuda_runtime.h>
#include <math.h>
#include <stdint.h>

// ---------------- problem constants ----------------
#define Bb     2
#define Ss     2048
#define DIMc   2048
#define Hh     16
#define QLORA  1536
#define KVLORA 512
#define NOPEc  128
#define ROPEc  64
#define VDIMc  128
#define QKH    192            // NOPE + ROPE
#define ROWS   (Bb*Ss)        // 4096
#define DF     576            // 512 latent + 64 rope
#define SCALEc 0.07216878364870322f  // 1/sqrt(192)
#define EPSc   1e-6f

// ---------------- scratch (static device arrays; no allocation) ----------------
__device__ float g_qlat[(size_t)ROWS * QLORA];          // 4096 x 1536
__device__ float g_q[(size_t)ROWS * (Hh * QKH)];        // 4096 x 3072
__device__ float g_kv[(size_t)ROWS * DF];               // 4096 x 576
__device__ float g_kfull[(size_t)ROWS * DF];            // 4096 x 576
__device__ float g_qfull[(size_t)ROWS * Hh * DF];       // 4096 x 16 x 576
__device__ float g_ctx[(size_t)ROWS * Hh * KVLORA];     // 4096 x 16 x 512
__device__ float g_attnout[(size_t)ROWS * DIMc];        // 4096 x 2048
__device__ float g_wkvbT[(size_t)Hh * KVLORA * NOPEc];  // 16 x 512 x 128 (transposed nope half)

// ================= tf32 helpers =================
__device__ __forceinline__ uint32_t f2tf(float x) {
    uint32_t r;
    asm("cvt.rna.tf32.f32 %0, %1;" : "=r"(r) : "f"(x));
    return r;
}
__device__ __forceinline__ float4 tf4(float4 v) {
    v.x = __uint_as_float(f2tf(v.x));
    v.y = __uint_as_float(f2tf(v.y));
    v.z = __uint_as_float(f2tf(v.z));
    v.w = __uint_as_float(f2tf(v.w));
    return v;
}
__device__ __forceinline__ void mma_tf32(float* d, const uint32_t* a, const uint32_t* b) {
    asm volatile(
        "mma.sync.aligned.m16n8k8.row.col.f32.tf32.tf32.f32 "
        "{%0,%1,%2,%3}, {%4,%5,%6,%7}, {%8,%9}, {%0,%1,%2,%3};"
        : "+f"(d[0]), "+f"(d[1]), "+f"(d[2]), "+f"(d[3])
        : "r"(a[0]), "r"(a[1]), "r"(a[2]), "r"(a[3]), "r"(b[0]), "r"(b[1]));
}

// ================= tf32 tensor-core GEMM (TB only: C = A @ B^T) =================
// A [M,K] row-major, B [N,K] row-major. Batched over grid.z (element strides).
// 128x128 tile, BK=16, 256 threads, warp tile 64x32.
// Smem: swizzled row-major  word(m,k) = m*16 + (k ^ ((m>>1)&3)*4).
//   - tile stores: conflict-free STS.128 (quarter-warp hits 8 distinct quads)
//   - fragment loads: conflict-free LDS.32 (bank = (g&1)*16 + ((K0|t)^((g>>1)<<2)))
__global__ __launch_bounds__(256) void gemm_tc_kernel(
    const float* __restrict__ A, int lda, long sA_,
    const float* __restrict__ B, int ldb, long sB_,
    float* __restrict__ C, int ldc, long sC_,
    int M, int N, int K)
{
    __shared__ __align__(16) uint32_t sA[2][2048];
    __shared__ __align__(16) uint32_t sB[2][2048];

    int z = blockIdx.z;
    A += (size_t)z * sA_;
    B += (size_t)z * sB_;
    C += (size_t)z * sC_;

    const int tid    = threadIdx.x;
    const int lane   = tid & 31;
    const int warp   = tid >> 5;
    const int warp_m = warp >> 2;      // 0..1
    const int warp_n = warp & 3;       // 0..3
    const int g = lane >> 2, t = lane & 3;
    const int m0 = blockIdx.y * 128;
    const int n0 = blockIdx.x * 128;
    const int KT = K >> 4;

    float acc[4][4][4];
#pragma unroll
    for (int mt = 0; mt < 4; mt++)
#pragma unroll
        for (int nt = 0; nt < 4; nt++)
#pragma unroll
            for (int e = 0; e < 4; e++) acc[mt][nt][e] = 0.f;

    float4 av[2], bv[2];
    // loader indices: row r = s>>2 (0..127), kc = (s&3)*4; swizzled col offset
    const int lr0 = tid >> 2;          // pass 0 row
    const int lkc = (tid & 3) << 2;    // k offset 0/4/8/12

    auto loadT = [&](int kt) {
        int k0 = kt << 4;
#pragma unroll
        for (int i = 0; i < 2; i++) {
            int r = lr0 + i * 64;
            av[i] = *(const float4*)(A + (size_t)(m0 + r) * lda + k0 + lkc);
            float4 v = make_float4(0.f, 0.f, 0.f, 0.f);
            if (n0 + r < N) v = *(const float4*)(B + (size_t)(n0 + r) * ldb + k0 + lkc);
            bv[i] = v;
        }
    };

    auto storeT = [&](int buf) {
#pragma unroll
        for (int i = 0; i < 2; i++) {
            int r = lr0 + i * 64;
            int xc = lkc ^ (((r >> 1) & 3) << 2);
            uint4 ta;
            ta.x = f2tf(av[i].x); ta.y = f2tf(av[i].y);
            ta.z = f2tf(av[i].z); ta.w = f2tf(av[i].w);
            *(uint4*)&sA[buf][r * 16 + xc] = ta;
            uint4 tb;
            tb.x = f2tf(bv[i].x); tb.y = f2tf(bv[i].y);
            tb.z = f2tf(bv[i].z); tb.w = f2tf(bv[i].w);
            *(uint4*)&sB[buf][r * 16 + xc] = tb;
        }
    };

    const int fr = (g >> 1) << 2;      // fragment-row swizzle (same for m and n rows)

    auto compute = [&](int buf) {
#pragma unroll
        for (int ks = 0; ks < 2; ks++) {
            const int xk  = ((ks << 3) | t) ^ fr;
            const int xk2 = xk ^ 4;
            uint32_t af[4][4];
            uint32_t bf[4][2];
#pragma unroll
            for (int mt = 0; mt < 4; mt++) {
                int base = (warp_m * 64 + mt * 16 + g) * 16;
                af[mt][0] = sA[buf][base + xk];
                af[mt][1] = sA[buf][base + 128 + xk];
                af[mt][2] = sA[buf][base + xk2];
                af[mt][3] = sA[buf][base + 128 + xk2];
            }
#pragma unroll
            for (int nt = 0; nt < 4; nt++) {
                int base = (warp_n * 32 + nt * 8 + g) * 16;
                bf[nt][0] = sB[buf][base + xk];
                bf[nt][1] = sB[buf][base + xk2];
            }
#pragma unroll
            for (int mt = 0; mt < 4; mt++)
#pragma unroll
                for (int nt = 0; nt < 4; nt++)
                    mma_tf32(acc[mt][nt], af[mt], bf[nt]);
        }
    };

    loadT(0);
    storeT(0);
    __syncthreads();
    if (KT > 1) loadT(1);

    for (int kt = 0; kt < KT; kt++) {
        int cur = kt & 1;
        compute(cur);
        if (kt + 1 < KT) storeT(1 - cur);
        __syncthreads();
        if (kt + 2 < KT) loadT(kt + 2);
    }

    // ---- epilogue ----
#pragma unroll
    for (int mt = 0; mt < 4; mt++) {
        int row0 = m0 + warp_m * 64 + mt * 16 + g;
#pragma unroll
        for (int nt = 0; nt < 4; nt++) {
            int col = n0 + warp_n * 32 + nt * 8 + 2 * t;
            if (col < N) {
                *(float2*)(C + (size_t)row0 * ldc + col) =
                    make_float2(acc[mt][nt][0], acc[mt][nt][1]);
                *(float2*)(C + (size_t)(row0 + 8) * ldc + col) =
                    make_float2(acc[mt][nt][2], acc[mt][nt][3]);
            }
        }
    }
}

// ---------------- transpose wkv_b nope half: out[h][c][d] = wkv_b[h*256+d][c] ----------------
__global__ __launch_bounds__(256) void transpose_wkvb_kernel(
    const float* __restrict__ w, float* __restrict__ out)
{
    __shared__ float tile[32][33];
    int h = blockIdx.z;
    int c0 = blockIdx.x * 32;   // latent dim 0..511
    int d0 = blockIdx.y * 32;   // nope dim 0..127
    int tx = threadIdx.x & 31, ty = threadIdx.x >> 5;  // 32 x 8
#pragma unroll
    for (int i = ty; i < 32; i += 8)
        tile[i][tx] = w[((size_t)h * 256 + d0 + i) * KVLORA + c0 + tx];
    __syncthreads();
#pragma unroll
    for (int i = ty; i < 32; i += 8)
        out[((size_t)h * KVLORA + c0 + i) * NOPEc + d0 + tx] = tile[tx][i];
}

// ---------------- RMSNorm (in-place, one block per row) ----------------
__global__ __launch_bounds__(256) void rmsnorm_kernel(
    float* __restrict__ x, const float* __restrict__ w, int L)
{
    __shared__ float sbuf[8];
    int row = blockIdx.x;
    float* xr = x + (size_t)row * L;
    float ss = 0.f;
    for (int i = threadIdx.x; i < L; i += 256) { float v = xr[i]; ss += v * v; }
#pragma unroll
    for (int o = 16; o; o >>= 1) ss += __shfl_xor_sync(0xffffffffu, ss, o);
    int warp = threadIdx.x >> 5, lane = threadIdx.x & 31;
    if (lane == 0) sbuf[warp] = ss;
    __syncthreads();
    if (threadIdx.x == 0) {
        float t = 0.f;
#pragma unroll
        for (int i = 0; i < 8; i++) t += sbuf[i];
        sbuf[0] = rsqrtf(t / (float)L + EPSc);
    }
    __syncthreads();
    float sc = sbuf[0];
    for (int i = threadIdx.x; i < L; i += 256) xr[i] = xr[i] * sc * w[i];
}

// ---------------- kv split: rmsnorm(latent) + rope(k_pe) -> kfull ----------------
__global__ __launch_bounds__(256) void kvprep_kernel(
    const float* __restrict__ kv, const float* __restrict__ w,
    const float* __restrict__ fcos, const float* __restrict__ fsin,
    float* __restrict__ kfull)
{
    __shared__ float sbuf[8];
    int row = blockIdx.x;
    int s = row & (Ss - 1);
    const float* kr = kv + (size_t)row * DF;
    float* kf = kfull + (size_t)row * DF;

    float ss = 0.f;
    for (int i = threadIdx.x; i < KVLORA; i += 256) { float v = kr[i]; ss += v * v; }
#pragma unroll
    for (int o = 16; o; o >>= 1) ss += __shfl_xor_sync(0xffffffffu, ss, o);
    int warp = threadIdx.x >> 5, lane = threadIdx.x & 31;
    if (lane == 0) sbuf[warp] = ss;
    __syncthreads();
    if (threadIdx.x == 0) {
        float t = 0.f;
#pragma unroll
        for (int i = 0; i < 8; i++) t += sbuf[i];
        sbuf[0] = rsqrtf(t / (float)KVLORA + EPSc);
    }
    __syncthreads();
    float sc = sbuf[0];
    for (int i = threadIdx.x; i < KVLORA; i += 256) kf[i] = kr[i] * sc * w[i];

    if (threadIdx.x < 32) {
        int i = threadIdx.x;
        float x0 = kr[KVLORA + 2 * i], x1 = kr[KVLORA + 2 * i + 1];
        float c = fcos[s * 32 + i], sn = fsin[s * 32 + i];
        kf[KVLORA + 2 * i]     = x0 * c - x1 * sn;
        kf[KVLORA + 2 * i + 1] = x0 * sn + x1 * c;
    }
}

// ---------------- rope(q_pe) -> qfull[:, :, 512:576] ----------------
__global__ __launch_bounds__(512) void ropeq_kernel(
    const float* __restrict__ q, const float* __restrict__ fcos,
    const float* __restrict__ fsin, float* __restrict__ qfull)
{
    int row = blockIdx.x;
    int s = row & (Ss - 1);
    int t = threadIdx.x;       // 512 = 16 heads * 32 pairs
    int h = t >> 5, i = t & 31;
    const float* qr = q + (size_t)row * (Hh * QKH) + h * QKH + NOPEc;
    float x0 = qr[2 * i], x1 = qr[2 * i + 1];
    float c = fcos[s * 32 + i], sn = fsin[s * 32 + i];
    float* dst = qfull + ((size_t)row * Hh + h) * DF + KVLORA;
    dst[2 * i]     = x0 * c - x1 * sn;
    dst[2 * i + 1] = x0 * sn + x1 * c;
}

// ---------------- flash attention (tf32 tensor core, 32q x 32k tiles) ----------------
#define KSTR 588
#define PSTR 36
#define ATTN_SMEM_BYTES ((2 * 32 * KSTR + 2 * 32 * PSTR + 64) * 4)

__global__ __launch_bounds__(256, 1) void attn_kernel(
    const float* __restrict__ qfull, const float* __restrict__ kfull,
    float* __restrict__ ctx)
{
    extern __shared__ float sm[];
    float* Qs   = sm;                   // 32 x 588 (tf32)
    float* Ks   = sm + 32 * KSTR;       // 32 x 588 (tf32; cols 0..511 double as V)
    float* Ps0  = Ks + 32 * KSTR;       // 32 x 36 (score partial wk=0; later P)
    float* Ps1  = Ps0 + 32 * PSTR;      // 32 x 36 (score partial wk=1)
    float* arow = Ps1 + 32 * PSTR;      // 32
    float* lrow = arow + 32;            // 32

    const int tid  = threadIdx.x;
    const int lane = tid & 31, warp = tid >> 5;
    const int g = lane >> 2, t = lane & 3;
    const int wk = warp & 1, wn = (warp >> 1) & 1, wm = warp >> 2;
    const int bh = blockIdx.y;
    const int b = bh >> 4, h = bh & 15;
    const int s0 = blockIdx.x * 32;

    // ---- load Q tile (tf32-rounded) ----
    {
        int qrow = tid >> 3, t8 = tid & 7;
        const float4* src = (const float4*)(qfull + ((size_t)(b * Ss + s0 + qrow) * Hh + h) * DF);
        float4* dst = (float4*)(Qs + qrow * KSTR);
#pragma unroll
        for (int c = 0; c < 18; c++) dst[t8 + c * 8] = tf4(src[t8 + c * 8]);
    }

    float oacc[2][8][4];
#pragma unroll
    for (int mt = 0; mt < 2; mt++)
#pragma unroll
        for (int nt = 0; nt < 8; nt++)
#pragma unroll
            for (int e = 0; e < 4; e++) oacc[mt][nt][e] = 0.f;

    float mreg[4], lreg[4];
#pragma unroll
    for (int ii = 0; ii < 4; ii++) { mreg[ii] = -INFINITY; lreg[ii] = 0.f; }

    const int ntiles = s0 / 32 + 1;
    for (int kt = 0; kt < ntiles; kt++) {
        int t0 = kt * 32;
        {
            int krow = tid >> 3, t8 = tid & 7;
            const float4* src = (const float4*)(kfull + (size_t)(b * Ss + t0 + krow) * DF);
            float4* dst = (float4*)(Ks + krow * KSTR);
#pragma unroll
            for (int c = 0; c < 18; c++) dst[t8 + c * 8] = tf4(src[t8 + c * 8]);
        }
        __syncthreads();

        // ---- scores: warp (wm,wn,wk) -> m16 x n16 tile, k-half wk ----
        {
            float sacc[2][4];
#pragma unroll
            for (int nt = 0; nt < 2; nt++)
#pragma unroll
                for (int e = 0; e < 4; e++) sacc[nt][e] = 0.f;

            const float* qb0 = Qs + (wm * 16 + g) * KSTR + wk * 288 + t;
#pragma unroll 4
            for (int ks = 0; ks < 36; ks++) {
                const float* qb = qb0 + ks * 8;
                uint32_t a[4];
                a[0] = __float_as_uint(qb[0]);
                a[1] = __float_as_uint(qb[8 * KSTR]);
                a[2] = __float_as_uint(qb[4]);
                a[3] = __float_as_uint(qb[8 * KSTR + 4]);
#pragma unroll
                for (int nt = 0; nt < 2; nt++) {
                    const float* kb = Ks + (wn * 16 + nt * 8 + g) * KSTR + wk * 288 + ks * 8 + t;
                    uint32_t bf[2];
                    bf[0] = __float_as_uint(kb[0]);
                    bf[1] = __float_as_uint(kb[4]);
                    mma_tf32(sacc[nt], a, bf);
                }
            }
            float* Pw = wk ? Ps1 : Ps0;
#pragma unroll
            for (int nt = 0; nt < 2; nt++) {
                int colb = wn * 16 + nt * 8 + 2 * t;
                *(float2*)&Pw[(wm * 16 + g) * PSTR + colb] =
                    make_float2(sacc[nt][0], sacc[nt][1]);
                *(float2*)&Pw[(wm * 16 + g + 8) * PSTR + colb] =
                    make_float2(sacc[nt][2], sacc[nt][3]);
            }
        }
        __syncthreads();

        // ---- softmax: warp owns rows 4*warp..+3, lane = key j ----
        {
#pragma unroll
            for (int ii = 0; ii < 4; ii++) {
                int i = warp * 4 + ii;
                float v = (Ps0[i * PSTR + lane] + Ps1[i * PSTR + lane]) * SCALEc;
                if (t0 + lane > s0 + i) v = -INFINITY;
                float mx = v;
#pragma unroll
                for (int o = 16; o; o >>= 1) mx = fmaxf(mx, __shfl_xor_sync(0xffffffffu, mx, o));
                float mnew = fmaxf(mreg[ii], mx);
                float p = __expf(v - mnew);
                float psum = p;
#pragma unroll
                for (int o = 16; o; o >>= 1) psum += __shfl_xor_sync(0xffffffffu, psum, o);
                float al = __expf(mreg[ii] - mnew);
                lreg[ii] = lreg[ii] * al + psum;
                mreg[ii] = mnew;
                Ps0[i * PSTR + lane] = __uint_as_float(f2tf(p));
                if (lane == 0) arow[i] = al;
            }
        }
        __syncthreads();

        // ---- PV: warp owns all 32 rows x cols [warp*64, warp*64+64) ----
        {
#pragma unroll
            for (int mt = 0; mt < 2; mt++) {
                float al0 = arow[mt * 16 + g];
                float al1 = arow[mt * 16 + g + 8];
#pragma unroll
                for (int nt = 0; nt < 8; nt++) {
                    oacc[mt][nt][0] *= al0; oacc[mt][nt][1] *= al0;
                    oacc[mt][nt][2] *= al1; oacc[mt][nt][3] *= al1;
                }
            }
#pragma unroll
            for (int jb = 0; jb < 4; jb++) {
                int j0 = jb * 8;
                uint32_t pa[2][4];
#pragma unroll
                for (int mt = 0; mt < 2; mt++) {
                    const float* pb = Ps0 + (mt * 16 + g) * PSTR + j0 + t;
                    pa[mt][0] = __float_as_uint(pb[0]);
                    pa[mt][1] = __float_as_uint(pb[8 * PSTR]);
                    pa[mt][2] = __float_as_uint(pb[4]);
                    pa[mt][3] = __float_as_uint(pb[8 * PSTR + 4]);
                }
#pragma unroll
                for (int nt = 0; nt < 8; nt++) {
                    const float* vbp = Ks + (j0 + t) * KSTR + warp * 64 + nt * 8 + g;
                    uint32_t vb[2];
                    vb[0] = __float_as_uint(vbp[0]);
                    vb[1] = __float_as_uint(vbp[4 * KSTR]);
                    mma_tf32(oacc[0][nt], pa[0], vb);
                    mma_tf32(oacc[1][nt], pa[1], vb);
                }
            }
        }
        __syncthreads();
    }

    // ---- publish l, normalize, store ctx ----
    if (lane == 0) {
#pragma unroll
        for (int ii = 0; ii < 4; ii++) lrow[warp * 4 + ii] = lreg[ii];
    }
    __syncthreads();
#pragma unroll
    for (int mt = 0; mt < 2; mt++) {
        int r0 = mt * 16 + g;
        int r1 = mt * 16 + g + 8;
        float inv0 = 1.0f / lrow[r0];
        float inv1 = 1.0f / lrow[r1];
        float* cp0 = ctx + ((size_t)(b * Ss + s0 + r0) * Hh + h) * KVLORA + warp * 64;
        float* cp1 = ctx + ((size_t)(b * Ss + s0 + r1) * Hh + h) * KVLORA + warp * 64;
#pragma unroll
        for (int nt = 0; nt < 8; nt++) {
            int col = nt * 8 + 2 * t;
            *(float2*)(cp0 + col) = make_float2(oacc[mt][nt][0] * inv0, oacc[mt][nt][1] * inv0);
            *(float2*)(cp1 + col) = make_float2(oacc[mt][nt][2] * inv1, oacc[mt][nt][3] * inv1);
        }
    }
}

// ---------------- launch ----------------
extern "C" void kernel_launch(void* const* d_in, const int* in_sizes, int n_in,
                              void* d_out, int out_size)
{
    const float* x     = (const float*)d_in[0];
    const float* fcos  = (const float*)d_in[1];
    const float* fsin  = (const float*)d_in[2];
    // d_in[3] = mask (causal; handled analytically)
    const float* wq_a  = (const float*)d_in[4];
    const float* q_ln  = (const float*)d_in[5];
    const float* wq_b  = (const float*)d_in[6];
    const float* wkv_a = (const float*)d_in[7];
    const float* kv_ln = (const float*)d_in[8];
    const float* wkv_b = (const float*)d_in[9];
    const float* wo    = (const float*)d_in[10];
    float* out = (float*)d_out;

    float *qlat, *q, *kv, *kfull, *qfull, *ctx, *attnout, *wkvbT;
    cudaGetSymbolAddress((void**)&qlat,    g_qlat);
    cudaGetSymbolAddress((void**)&q,       g_q);
    cudaGetSymbolAddress((void**)&kv,      g_kv);
    cudaGetSymbolAddress((void**)&kfull,   g_kfull);
    cudaGetSymbolAddress((void**)&qfull,   g_qfull);
    cudaGetSymbolAddress((void**)&ctx,     g_ctx);
    cudaGetSymbolAddress((void**)&attnout, g_attnout);
    cudaGetSymbolAddress((void**)&wkvbT,   g_wkvbT);

    dim3 blk(256);

    // 0. transpose wkv_b nope half -> wkvbT[h][512][128]
    transpose_wkvb_kernel<<<dim3(KVLORA / 32, NOPEc / 32, Hh), blk>>>(wkv_b, wkvbT);

    // 1. q_lat_pre = x @ wq_a^T      (4096 x 1536, K=2048)
    gemm_tc_kernel<<<dim3(QLORA / 128, ROWS / 128, 1), blk>>>(
        x, DIMc, 0, wq_a, DIMc, 0, qlat, QLORA, 0, ROWS, QLORA, DIMc);

    // 2. rmsnorm in place
    rmsnorm_kernel<<<ROWS, 256>>>(qlat, q_ln, QLORA);

    // 3. q = q_lat @ wq_b^T          (4096 x 3072, K=1536)
    gemm_tc_kernel<<<dim3((Hh * QKH) / 128, ROWS / 128, 1), blk>>>(
        qlat, QLORA, 0, wq_b, QLORA, 0, q, Hh * QKH, 0, ROWS, Hh * QKH, QLORA);

    // 4. kv = x @ wkv_a^T            (4096 x 576, K=2048)
    gemm_tc_kernel<<<dim3((DF + 127) / 128, ROWS / 128, 1), blk>>>(
        x, DIMc, 0, wkv_a, DIMc, 0, kv, DF, 0, ROWS, DF, DIMc);

    // 5. kfull = [rmsnorm(kv_lat), rope(k_pe)]
    kvprep_kernel<<<ROWS, 256>>>(kv, kv_ln, fcos, fsin, kfull);

    // 6. q-absorb per head: qfull[:, h, :512] = q_nope_h @ wkvbT[h]^T (TB, batched over heads)
    gemm_tc_kernel<<<dim3(KVLORA / 128, ROWS / 128, Hh), blk>>>(
        q, Hh * QKH, QKH,
        wkvbT, NOPEc, (long)KVLORA * NOPEc,
        qfull, Hh * DF, DF,
        ROWS, KVLORA, NOPEc);

    // 7. qfull[:, h, 512:576] = rope(q_pe)
    ropeq_kernel<<<ROWS, 512>>>(q, fcos, fsin, qfull);

    // 8. flash attention -> ctx (B,S,H,512), tf32 tensor cores
    cudaFuncSetAttribute(attn_kernel, cudaFuncAttributeMaxDynamicSharedMemorySize,
                         ATTN_SMEM_BYTES);
    attn_kernel<<<dim3(Ss / 32, Bb * Hh), 256, ATTN_SMEM_BYTES>>>(qfull, kfull, ctx);

    // 9. per-head out-proj: attnout[:, h*128:(h+1)*128] = ctx_h @ wkv_b3[h, 128:256, :]^T (TB, batched)
    gemm_tc_kernel<<<dim3(1, ROWS / 128, Hh), blk>>>(
        ctx, Hh * KVLORA, KVLORA,
        wkv_b + (size_t)NOPEc * KVLORA, KVLORA, (long)(NOPEc + VDIMc) * KVLORA,
        attnout, DIMc, VDIMc,
        ROWS, VDIMc, KVLORA);

    // 10. out = attnout @ wo^T       (4096 x 2048, K=2048)
    gemm_tc_kernel<<<dim3(DIMc / 128, ROWS / 128, 1), blk>>>(
        attnout, DIMc, 0, wo, DIMc, 0, out, DIMc, 0, ROWS, DIMc, DIMc);
}